// round 4
// baseline (speedup 1.0000x reference)
#include <cuda_runtime.h>
#include <cuda_bf16.h>

#define NH 10
#define NT 5
#define NS 10
#define FULLM 0xffffffffu

// MUFU.TANH (sm_75+): single-instruction tanh.
__device__ __forceinline__ float mtanh(float x) {
    float y;
    asm("tanh.approx.f32 %0, %1;" : "=f"(y) : "f"(x));
    return y;
}
// sigmoid(x) = 0.5*tanh(x/2) + 0.5
__device__ __forceinline__ float fsig(float x) {
    return fmaf(0.5f, mtanh(0.5f * x), 0.5f);
}

__global__ void __launch_bounds__(160, 1)
rnnae_kernel(const float* __restrict__ omega,
             const float* __restrict__ noise,
             const void*  __restrict__ go1_raw,
             const void*  __restrict__ go2_raw,
             const float* __restrict__ W_ih,   // [40,2]
             const float* __restrict__ W_hh,   // [40,10]
             const float* __restrict__ b_ih,   // [40]
             const float* __restrict__ b_hh,   // [40]
             const float* __restrict__ w1,     // [20,10]
             const float* __restrict__ b1,     // [20]
             const float* __restrict__ w2,     // [20,20]
             const float* __restrict__ b2,     // [20]
             const float* __restrict__ w3,     // [1,20]
             const float* __restrict__ b3,     // [1]
             float* __restrict__ out)
{
    __shared__ float sErr[NT];

    const int tid  = threadIdx.x;
    const int warp = tid >> 5;
    const int lane = tid & 31;
    const int j = (lane < NH) ? lane : 0;   // hidden index owned by this lane
    const int m = (lane < 20) ? lane : 0;   // MLP index owned by this lane

    // ============ vectorized global -> register prologue ==================
    // All input bases are 256B-aligned allocations.
    // W_ih rows: 2 floats at 8-byte offsets -> float2.
    float2 vi = *(const float2*)(W_ih + 2*j);
    float2 vf = *(const float2*)(W_ih + 2*(10+j));
    float2 vg = *(const float2*)(W_ih + 2*(20+j));
    float2 vo = *(const float2*)(W_ih + 2*(30+j));

    // W_hh rows: 10 floats at 40-byte offsets -> 5x float2 each.
    float whh_i[NH], whh_f[NH], whh_g[NH], whh_o[NH], rw1[NH];
    #pragma unroll
    for (int k = 0; k < 5; k++) {
        float2 a = *(const float2*)(W_hh + j*NH + 2*k);
        float2 b = *(const float2*)(W_hh + (10+j)*NH + 2*k);
        float2 cc = *(const float2*)(W_hh + (20+j)*NH + 2*k);
        float2 d = *(const float2*)(W_hh + (30+j)*NH + 2*k);
        float2 e = *(const float2*)(w1 + m*NH + 2*k);
        whh_i[2*k] = a.x; whh_i[2*k+1] = a.y;
        whh_f[2*k] = b.x; whh_f[2*k+1] = b.y;
        whh_g[2*k] = cc.x; whh_g[2*k+1] = cc.y;
        whh_o[2*k] = d.x; whh_o[2*k+1] = d.y;
        rw1[2*k] = e.x;  rw1[2*k+1] = e.y;
    }

    float bi = b_ih[j]    + b_hh[j];
    float bf = b_ih[10+j] + b_hh[10+j];
    float bg = b_ih[20+j] + b_hh[20+j];
    float bo = b_ih[30+j] + b_hh[30+j];

    // w2 rows: 20 floats at 80-byte offsets -> 5x float4. w3: 5x float4 bcast.
    float rw2[20], rw3[20];
    #pragma unroll
    for (int k = 0; k < 5; k++) {
        float4 a = *(const float4*)(w2 + m*20 + 4*k);
        float4 b = *(const float4*)(w3 + 4*k);
        rw2[4*k] = a.x; rw2[4*k+1] = a.y; rw2[4*k+2] = a.z; rw2[4*k+3] = a.w;
        rw3[4*k] = b.x; rw3[4*k+1] = b.y; rw3[4*k+2] = b.z; rw3[4*k+3] = b.w;
    }
    float rb1 = b1[m], rb2 = b2[m], rb3 = b3[0];

    const float om = omega[warp];

    // noise row: 40-byte offset -> 5x float2.
    float nz[NS];
    #pragma unroll
    for (int k = 0; k < 5; k++) {
        float2 a = *(const float2*)(noise + warp*NS + 2*k);
        nz[2*k] = a.x; nz[2*k+1] = a.y;
    }

    // masks: 10 words = uint4 + uint4 + uint2 (base 256B-aligned). Decode
    // storage dtype (float32 / int32 / packed uint8) redundantly per lane.
    unsigned int mw1[10], mw2[10];
    {
        const uint4* p1 = (const uint4*)go1_raw;
        const uint4* p2 = (const uint4*)go2_raw;
        uint4 a = p1[0], b = p1[1];
        uint2 c1 = *(const uint2*)((const unsigned int*)go1_raw + 8);
        uint4 d = p2[0], e = p2[1];
        uint2 c2 = *(const uint2*)((const unsigned int*)go2_raw + 8);
        mw1[0]=a.x; mw1[1]=a.y; mw1[2]=a.z; mw1[3]=a.w;
        mw1[4]=b.x; mw1[5]=b.y; mw1[6]=b.z; mw1[7]=b.w;
        mw1[8]=c1.x; mw1[9]=c1.y;
        mw2[0]=d.x; mw2[1]=d.y; mw2[2]=d.z; mw2[3]=d.w;
        mw2[4]=e.x; mw2[5]=e.y; mw2[6]=e.z; mw2[7]=e.w;
        mw2[8]=c2.x; mw2[9]=c2.y;
    }
    int mm1[10], mm2[10];
    {
        bool w32_1 = true, w32_2 = true;   // words are valid f32/i32 {0,1} pattern
        #pragma unroll
        for (int i = 0; i < 10; i++) {
            unsigned int v1 = mw1[i], v2 = mw2[i];
            if (v1 != 0u && v1 != 0x3F800000u && v1 != 1u) w32_1 = false;
            if (v2 != 0u && v2 != 0x3F800000u && v2 != 1u) w32_2 = false;
        }
        if (w32_1) { for (int i = 0; i < 10; i++) mm1[i] = (mw1[i] != 0u); }
        else { const unsigned char* b = (const unsigned char*)mw1;
               for (int i = 0; i < 10; i++) mm1[i] = (b[i] != 0); }
        if (w32_2) { for (int i = 0; i < 10; i++) mm2[i] = (mw2[i] != 0u); }
        else { const unsigned char* b = (const unsigned char*)mw2;
               for (int i = 0; i < 10; i++) mm2[i] = (b[i] != 0); }
    }

    // human actions
    float ahr[NS];
    {
        bool g1 = (fabsf(om - 0.4f) < 1e-3f) || (fabsf(om - 0.8f) < 1e-3f);
        float scale = g1 ? 0.2f : 0.4f;
        float base = (om - 0.6f) / scale;
        #pragma unroll
        for (int t = 0; t < NS; t++) {
            int tm = g1 ? mm1[t] : mm2[t];
            ahr[t] = (tm ? base : 0.0f) + nz[t];
        }
    }

    // ================= rollout: registers + shfl only ======================
    float s = 0.0f, c = 0.0f, err = 0.0f;
    float hh[NH];
    #pragma unroll
    for (int k = 0; k < NH; k++) hh[k] = 0.0f;

    #pragma unroll
    for (int t = 0; t < NS; t++) {
        float ah = ahr[t];

        float gia = fmaf(ah, vi.y, bi), gib = 0.0f;
        float gfa = fmaf(ah, vf.y, bf), gfb = 0.0f;
        float gga = fmaf(ah, vg.y, bg), ggb = 0.0f;
        float goa = fmaf(ah, vo.y, bo), gob = 0.0f;
        #pragma unroll
        for (int k = 0; k < 5; k++) {
            gia = fmaf(hh[k], whh_i[k], gia);  gib = fmaf(hh[k+5], whh_i[k+5], gib);
            gfa = fmaf(hh[k], whh_f[k], gfa);  gfb = fmaf(hh[k+5], whh_f[k+5], gfb);
            gga = fmaf(hh[k], whh_g[k], gga);  ggb = fmaf(hh[k+5], whh_g[k+5], ggb);
            goa = fmaf(hh[k], whh_o[k], goa);  gob = fmaf(hh[k+5], whh_o[k+5], gob);
        }
        float gi = fsig (fmaf(s, vi.x, gia + gib));
        float gf = fsig (fmaf(s, vf.x, gfa + gfb));
        float gg = mtanh(fmaf(s, vg.x, gga + ggb));
        float go = fsig (fmaf(s, vo.x, goa + gob));
        c = fmaf(gf, c, gi * gg);
        float h = go * mtanh(c);

        #pragma unroll
        for (int k = 0; k < NH; k++) hh[k] = __shfl_sync(FULLM, h, k);

        float h1a = rb1, h1b = 0.0f;
        #pragma unroll
        for (int k = 0; k < 5; k++) {
            h1a = fmaf(hh[k],   rw1[k],   h1a);
            h1b = fmaf(hh[k+5], rw1[k+5], h1b);
        }
        float h1 = fmaxf(h1a + h1b, 0.0f);

        float g1v[20];
        #pragma unroll
        for (int k = 0; k < 20; k++) g1v[k] = __shfl_sync(FULLM, h1, k);

        float h2a = rb2, h2b = 0.0f, h2c = 0.0f, h2d = 0.0f;
        #pragma unroll
        for (int k = 0; k < 5; k++) {
            h2a = fmaf(g1v[k],    rw2[k],    h2a);
            h2b = fmaf(g1v[k+5],  rw2[k+5],  h2b);
            h2c = fmaf(g1v[k+10], rw2[k+10], h2c);
            h2d = fmaf(g1v[k+15], rw2[k+15], h2d);
        }
        float h2 = fmaxf((h2a + h2b) + (h2c + h2d), 0.0f);

        float g2v[20];
        #pragma unroll
        for (int k = 0; k < 20; k++) g2v[k] = __shfl_sync(FULLM, h2, k);

        float ra = rb3, rb = 0.0f, rc = 0.0f, rd = 0.0f;
        #pragma unroll
        for (int k = 0; k < 5; k++) {
            ra = fmaf(g2v[k],    rw3[k],    ra);
            rb = fmaf(g2v[k+5],  rw3[k+5],  rb);
            rc = fmaf(g2v[k+10], rw3[k+10], rc);
            rd = fmaf(g2v[k+15], rw3[k+15], rd);
        }
        float ar = (ra + rb) + (rc + rd);

        s += ar;
        float d = s - om;
        err = fmaf(d, d, err);
    }

    if (lane == 0) sErr[warp] = err;
    __syncthreads();
    if (tid == 0) {
        out[0] = ((sErr[0] + sErr[1]) + (sErr[2] + sErr[3])) + sErr[4];
    }
}

extern "C" void kernel_launch(void* const* d_in, const int* in_sizes, int n_in,
                              void* d_out, int out_size) {
    const float* omega = (const float*)d_in[0];
    const float* noise = (const float*)d_in[1];
    const void*  go1   = (const void*)d_in[2];
    const void*  go2   = (const void*)d_in[3];
    const float* W_ih  = (const float*)d_in[4];
    const float* W_hh  = (const float*)d_in[5];
    const float* b_ih  = (const float*)d_in[6];
    const float* b_hh  = (const float*)d_in[7];
    const float* w1    = (const float*)d_in[8];
    const float* b1    = (const float*)d_in[9];
    const float* w2    = (const float*)d_in[10];
    const float* b2    = (const float*)d_in[11];
    const float* w3    = (const float*)d_in[12];
    const float* b3    = (const float*)d_in[13];
    float* out = (float*)d_out;

    rnnae_kernel<<<1, 160>>>(omega, noise, go1, go2, W_ih, W_hh, b_ih, b_hh,
                             w1, b1, w2, b2, w3, b3, out);
}

// round 6
// speedup vs baseline: 1.2330x; 1.2330x over previous
#include <cuda_runtime.h>
#include <cuda_bf16.h>

#define NH 10
#define NT 5
#define NS 10
#define FULLM 0xffffffffu

// MUFU.TANH: single-instruction tanh.
__device__ __forceinline__ float mtanh(float x) {
    float y;
    asm("tanh.approx.f32 %0, %1;" : "=f"(y) : "f"(x));
    return y;
}
// sigmoid(x) = 0.5*tanh(x/2) + 0.5
__device__ __forceinline__ float fsig(float x) {
    return fmaf(0.5f, mtanh(0.5f * x), 0.5f);
}

// cross-block reduction scratch (alloc-free: __device__ globals)
__device__ float g_err[NT];
__device__ int   g_cnt = 0;

__global__ void __launch_bounds__(32, 1)
rnnae_kernel(const float* __restrict__ omega,
             const float* __restrict__ noise,
             const void*  __restrict__ go1_raw,
             const void*  __restrict__ go2_raw,
             const float* __restrict__ W_ih,   // [40,2]
             const float* __restrict__ W_hh,   // [40,10]
             const float* __restrict__ b_ih,   // [40]
             const float* __restrict__ b_hh,   // [40]
             const float* __restrict__ w1,     // [20,10]
             const float* __restrict__ b1,     // [20]
             const float* __restrict__ w2,     // [20,20]
             const float* __restrict__ b2,     // [20]
             const float* __restrict__ w3,     // [1,20]
             const float* __restrict__ b3,     // [1]
             float* __restrict__ out)
{
    const int task = blockIdx.x;            // one task per block (per SM)
    const int lane = threadIdx.x;
    const int j = (lane < NH) ? lane : 0;   // hidden index owned by this lane
    const int m = (lane < 20) ? lane : 0;   // MLP index owned by this lane

    // ============ vectorized global -> register prologue ==================
    float2 vi = *(const float2*)(W_ih + 2*j);
    float2 vf = *(const float2*)(W_ih + 2*(10+j));
    float2 vg = *(const float2*)(W_ih + 2*(20+j));
    float2 vo = *(const float2*)(W_ih + 2*(30+j));

    float whh_i[NH], whh_f[NH], whh_g[NH], whh_o[NH], rw1[NH];
    #pragma unroll
    for (int k = 0; k < 5; k++) {
        float2 a  = *(const float2*)(W_hh + j*NH + 2*k);
        float2 b  = *(const float2*)(W_hh + (10+j)*NH + 2*k);
        float2 cc = *(const float2*)(W_hh + (20+j)*NH + 2*k);
        float2 d  = *(const float2*)(W_hh + (30+j)*NH + 2*k);
        float2 e  = *(const float2*)(w1 + m*NH + 2*k);
        whh_i[2*k] = a.x;  whh_i[2*k+1] = a.y;
        whh_f[2*k] = b.x;  whh_f[2*k+1] = b.y;
        whh_g[2*k] = cc.x; whh_g[2*k+1] = cc.y;
        whh_o[2*k] = d.x;  whh_o[2*k+1] = d.y;
        rw1[2*k]   = e.x;  rw1[2*k+1]   = e.y;
    }

    float bi = b_ih[j]    + b_hh[j];
    float bf = b_ih[10+j] + b_hh[10+j];
    float bg = b_ih[20+j] + b_hh[20+j];
    float bo = b_ih[30+j] + b_hh[30+j];

    float rw2[20], rw3[20];
    #pragma unroll
    for (int k = 0; k < 5; k++) {
        float4 a = *(const float4*)(w2 + m*20 + 4*k);
        float4 b = *(const float4*)(w3 + 4*k);
        rw2[4*k] = a.x; rw2[4*k+1] = a.y; rw2[4*k+2] = a.z; rw2[4*k+3] = a.w;
        rw3[4*k] = b.x; rw3[4*k+1] = b.y; rw3[4*k+2] = b.z; rw3[4*k+3] = b.w;
    }
    float rb1 = b1[m], rb2 = b2[m], rb3 = b3[0];

    const float om = omega[task];

    float nz[NS];
    #pragma unroll
    for (int k = 0; k < 5; k++) {
        float2 a = *(const float2*)(noise + task*NS + 2*k);
        nz[2*k] = a.x; nz[2*k+1] = a.y;
    }

    // masks (dtype-agnostic decode: f32 / i32 / packed u8)
    unsigned int mw1[10], mw2[10];
    {
        const uint4* p1 = (const uint4*)go1_raw;
        const uint4* p2 = (const uint4*)go2_raw;
        uint4 a = p1[0], b = p1[1];
        uint2 c1 = *(const uint2*)((const unsigned int*)go1_raw + 8);
        uint4 d = p2[0], e = p2[1];
        uint2 c2 = *(const uint2*)((const unsigned int*)go2_raw + 8);
        mw1[0]=a.x; mw1[1]=a.y; mw1[2]=a.z; mw1[3]=a.w;
        mw1[4]=b.x; mw1[5]=b.y; mw1[6]=b.z; mw1[7]=b.w;
        mw1[8]=c1.x; mw1[9]=c1.y;
        mw2[0]=d.x; mw2[1]=d.y; mw2[2]=d.z; mw2[3]=d.w;
        mw2[4]=e.x; mw2[5]=e.y; mw2[6]=e.z; mw2[7]=e.w;
        mw2[8]=c2.x; mw2[9]=c2.y;
    }
    int mm1[10], mm2[10];
    {
        bool w32_1 = true, w32_2 = true;
        #pragma unroll
        for (int i = 0; i < 10; i++) {
            unsigned int v1 = mw1[i], v2 = mw2[i];
            if (v1 != 0u && v1 != 0x3F800000u && v1 != 1u) w32_1 = false;
            if (v2 != 0u && v2 != 0x3F800000u && v2 != 1u) w32_2 = false;
        }
        if (w32_1) { for (int i = 0; i < 10; i++) mm1[i] = (mw1[i] != 0u); }
        else { const unsigned char* b = (const unsigned char*)mw1;
               for (int i = 0; i < 10; i++) mm1[i] = (b[i] != 0); }
        if (w32_2) { for (int i = 0; i < 10; i++) mm2[i] = (mw2[i] != 0u); }
        else { const unsigned char* b = (const unsigned char*)mw2;
               for (int i = 0; i < 10; i++) mm2[i] = (b[i] != 0); }
    }

    float ahr[NS];
    {
        bool g1 = (fabsf(om - 0.4f) < 1e-3f) || (fabsf(om - 0.8f) < 1e-3f);
        float scale = g1 ? 0.2f : 0.4f;
        float base = (om - 0.6f) / scale;
        #pragma unroll
        for (int t = 0; t < NS; t++) {
            int tm = g1 ? mm1[t] : mm2[t];
            ahr[t] = (tm ? base : 0.0f) + nz[t];
        }
    }

    // ================= rollout: registers + shfl only ======================
    float s = 0.0f, c = 0.0f, err = 0.0f;
    float hh[NH];
    #pragma unroll
    for (int k = 0; k < NH; k++) hh[k] = 0.0f;

    #pragma unroll
    for (int t = 0; t < NS; t++) {
        float ah = ahr[t];

        float gia = fmaf(ah, vi.y, bi), gib = 0.0f;
        float gfa = fmaf(ah, vf.y, bf), gfb = 0.0f;
        float gga = fmaf(ah, vg.y, bg), ggb = 0.0f;
        float goa = fmaf(ah, vo.y, bo), gob = 0.0f;
        #pragma unroll
        for (int k = 0; k < 5; k++) {
            gia = fmaf(hh[k], whh_i[k], gia);  gib = fmaf(hh[k+5], whh_i[k+5], gib);
            gfa = fmaf(hh[k], whh_f[k], gfa);  gfb = fmaf(hh[k+5], whh_f[k+5], gfb);
            gga = fmaf(hh[k], whh_g[k], gga);  ggb = fmaf(hh[k+5], whh_g[k+5], ggb);
            goa = fmaf(hh[k], whh_o[k], goa);  gob = fmaf(hh[k+5], whh_o[k+5], gob);
        }
        float gi = fsig (fmaf(s, vi.x, gia + gib));
        float gf = fsig (fmaf(s, vf.x, gfa + gfb));
        float gg = mtanh(fmaf(s, vg.x, gga + ggb));
        float go = fsig (fmaf(s, vo.x, goa + gob));
        c = fmaf(gf, c, gi * gg);
        float h = go * mtanh(c);

        // comm round 1: gather h
        #pragma unroll
        for (int k = 0; k < NH; k++) hh[k] = __shfl_sync(FULLM, h, k);

        float h1a = rb1, h1b = 0.0f;
        #pragma unroll
        for (int k = 0; k < 5; k++) {
            h1a = fmaf(hh[k],   rw1[k],   h1a);
            h1b = fmaf(hh[k+5], rw1[k+5], h1b);
        }
        float h1 = fmaxf(h1a + h1b, 0.0f);

        // comm round 2: gather h1
        float g1v[20];
        #pragma unroll
        for (int k = 0; k < 20; k++) g1v[k] = __shfl_sync(FULLM, h1, k);

        float h2a = rb2, h2b = 0.0f, h2c = 0.0f, h2d = 0.0f;
        #pragma unroll
        for (int k = 0; k < 5; k++) {
            h2a = fmaf(g1v[k],    rw2[k],    h2a);
            h2b = fmaf(g1v[k+5],  rw2[k+5],  h2b);
            h2c = fmaf(g1v[k+10], rw2[k+10], h2c);
            h2d = fmaf(g1v[k+15], rw2[k+15], h2d);
        }
        float h2 = fmaxf((h2a + h2b) + (h2c + h2d), 0.0f);

        // comm round 3: gather h2, redundant dot in all lanes
        float g2v[20];
        #pragma unroll
        for (int k = 0; k < 20; k++) g2v[k] = __shfl_sync(FULLM, h2, k);

        float ra = rb3, rb = 0.0f, rc = 0.0f, rd = 0.0f;
        #pragma unroll
        for (int k = 0; k < 5; k++) {
            ra = fmaf(g2v[k],    rw3[k],    ra);
            rb = fmaf(g2v[k+5],  rw3[k+5],  rb);
            rc = fmaf(g2v[k+10], rw3[k+10], rc);
            rd = fmaf(g2v[k+15], rw3[k+15], rd);
        }
        float ar = (ra + rb) + (rc + rd);

        s += ar;
        float d = s - om;
        err = fmaf(d, d, err);
    }

    // ============ deterministic cross-block reduction (last block) ========
    if (lane == 0) {
        g_err[task] = err;
        __threadfence();
        int old = atomicAdd(&g_cnt, 1);
        if (old == NT - 1) {
            // last arriving block: fixed-order sum -> deterministic bits
            float q = 0.0f;
            #pragma unroll
            for (int i = 0; i < NT; i++) {
                float v;
                asm volatile("ld.global.cg.f32 %0, [%1];" : "=f"(v) : "l"(g_err + i));
                q += v;
            }
            out[0] = q;
            g_cnt = 0;   // reset for next (graph-replayed) call
        }
    }
}

extern "C" void kernel_launch(void* const* d_in, const int* in_sizes, int n_in,
                              void* d_out, int out_size) {
    const float* omega = (const float*)d_in[0];
    const float* noise = (const float*)d_in[1];
    const void*  go1   = (const void*)d_in[2];
    const void*  go2   = (const void*)d_in[3];
    const float* W_ih  = (const float*)d_in[4];
    const float* W_hh  = (const float*)d_in[5];
    const float* b_ih  = (const float*)d_in[6];
    const float* b_hh  = (const float*)d_in[7];
    const float* w1    = (const float*)d_in[8];
    const float* b1    = (const float*)d_in[9];
    const float* w2    = (const float*)d_in[10];
    const float* b2    = (const float*)d_in[11];
    const float* w3    = (const float*)d_in[12];
    const float* b3    = (const float*)d_in[13];
    float* out = (float*)d_out;

    rnnae_kernel<<<NT, 32>>>(omega, noise, go1, go2, W_ih, W_hh, b_ih, b_hh,
                             w1, b1, w2, b2, w3, b3, out);
}

// round 7
// speedup vs baseline: 1.2647x; 1.0257x over previous
#include <cuda_runtime.h>
#include <cuda_bf16.h>

#define NH 10
#define NT 5
#define NS 10
#define FULLM 0xffffffffu

// MUFU.TANH: single-instruction tanh.
__device__ __forceinline__ float mtanh(float x) {
    float y;
    asm("tanh.approx.f32 %0, %1;" : "=f"(y) : "f"(x));
    return y;
}
// sigmoid with the 0.5 input pre-scale folded into the weights:
// caller passes z = 0.5*x  ->  sigma(x) = 0.5*tanh(z) + 0.5
__device__ __forceinline__ float fsig_pre(float z) {
    return fmaf(0.5f, mtanh(z), 0.5f);
}

// cross-block reduction scratch (alloc-free: __device__ globals)
__device__ unsigned long long g_sum = 0ull;   // fixed-point sum (err * 2^32)
__device__ unsigned int       g_cnt = 0u;

__global__ void __launch_bounds__(32, 1)
rnnae_kernel(const float* __restrict__ omega,
             const float* __restrict__ noise,
             const void*  __restrict__ go1_raw,
             const void*  __restrict__ go2_raw,
             const float* __restrict__ W_ih,   // [40,2]
             const float* __restrict__ W_hh,   // [40,10]
             const float* __restrict__ b_ih,   // [40]
             const float* __restrict__ b_hh,   // [40]
             const float* __restrict__ w1,     // [20,10]
             const float* __restrict__ b1,     // [20]
             const float* __restrict__ w2,     // [20,20]
             const float* __restrict__ b2,     // [20]
             const float* __restrict__ w3,     // [1,20]
             const float* __restrict__ b3,     // [1]
             float* __restrict__ out)
{
    const int task = blockIdx.x;            // one task per block (per SM)
    const int lane = threadIdx.x;
    const int j = (lane < NH) ? lane : 0;   // hidden index owned by this lane
    const int m = (lane < 20) ? lane : 0;   // MLP index owned by this lane

    // ============ vectorized global -> register prologue ==================
    // sigmoid gates (i,f,o) are pre-scaled by 0.5; tanh gate (g) is not.
    float2 vi = *(const float2*)(W_ih + 2*j);
    float2 vf = *(const float2*)(W_ih + 2*(10+j));
    float2 vg = *(const float2*)(W_ih + 2*(20+j));
    float2 vo = *(const float2*)(W_ih + 2*(30+j));
    vi.x *= 0.5f; vi.y *= 0.5f;
    vf.x *= 0.5f; vf.y *= 0.5f;
    vo.x *= 0.5f; vo.y *= 0.5f;

    float whh_i[NH], whh_f[NH], whh_g[NH], whh_o[NH], rw1[NH];
    #pragma unroll
    for (int k = 0; k < 5; k++) {
        float2 a  = *(const float2*)(W_hh + j*NH + 2*k);
        float2 b  = *(const float2*)(W_hh + (10+j)*NH + 2*k);
        float2 cc = *(const float2*)(W_hh + (20+j)*NH + 2*k);
        float2 d  = *(const float2*)(W_hh + (30+j)*NH + 2*k);
        float2 e  = *(const float2*)(w1 + m*NH + 2*k);
        whh_i[2*k] = 0.5f*a.x;  whh_i[2*k+1] = 0.5f*a.y;
        whh_f[2*k] = 0.5f*b.x;  whh_f[2*k+1] = 0.5f*b.y;
        whh_g[2*k] = cc.x;      whh_g[2*k+1] = cc.y;
        whh_o[2*k] = 0.5f*d.x;  whh_o[2*k+1] = 0.5f*d.y;
        rw1[2*k]   = e.x;       rw1[2*k+1]   = e.y;
    }

    float bi = 0.5f*(b_ih[j]    + b_hh[j]);
    float bf = 0.5f*(b_ih[10+j] + b_hh[10+j]);
    float bg =       b_ih[20+j] + b_hh[20+j];
    float bo = 0.5f*(b_ih[30+j] + b_hh[30+j]);

    float rw2[20], rw3[20];
    #pragma unroll
    for (int k = 0; k < 5; k++) {
        float4 a = *(const float4*)(w2 + m*20 + 4*k);
        float4 b = *(const float4*)(w3 + 4*k);
        rw2[4*k] = a.x; rw2[4*k+1] = a.y; rw2[4*k+2] = a.z; rw2[4*k+3] = a.w;
        rw3[4*k] = b.x; rw3[4*k+1] = b.y; rw3[4*k+2] = b.z; rw3[4*k+3] = b.w;
    }
    float rb1 = b1[m], rb2 = b2[m], rb3 = b3[0];

    const float om = omega[task];

    float nz[NS];
    #pragma unroll
    for (int k = 0; k < 5; k++) {
        float2 a = *(const float2*)(noise + task*NS + 2*k);
        nz[2*k] = a.x; nz[2*k+1] = a.y;
    }

    // masks (dtype-agnostic decode: f32 / i32 / packed u8)
    unsigned int mw1[10], mw2[10];
    {
        const uint4* p1 = (const uint4*)go1_raw;
        const uint4* p2 = (const uint4*)go2_raw;
        uint4 a = p1[0], b = p1[1];
        uint2 c1 = *(const uint2*)((const unsigned int*)go1_raw + 8);
        uint4 d = p2[0], e = p2[1];
        uint2 c2 = *(const uint2*)((const unsigned int*)go2_raw + 8);
        mw1[0]=a.x; mw1[1]=a.y; mw1[2]=a.z; mw1[3]=a.w;
        mw1[4]=b.x; mw1[5]=b.y; mw1[6]=b.z; mw1[7]=b.w;
        mw1[8]=c1.x; mw1[9]=c1.y;
        mw2[0]=d.x; mw2[1]=d.y; mw2[2]=d.z; mw2[3]=d.w;
        mw2[4]=e.x; mw2[5]=e.y; mw2[6]=e.z; mw2[7]=e.w;
        mw2[8]=c2.x; mw2[9]=c2.y;
    }
    int mm1[10], mm2[10];
    {
        bool w32_1 = true, w32_2 = true;
        #pragma unroll
        for (int i = 0; i < 10; i++) {
            unsigned int v1 = mw1[i], v2 = mw2[i];
            if (v1 != 0u && v1 != 0x3F800000u && v1 != 1u) w32_1 = false;
            if (v2 != 0u && v2 != 0x3F800000u && v2 != 1u) w32_2 = false;
        }
        if (w32_1) { for (int i = 0; i < 10; i++) mm1[i] = (mw1[i] != 0u); }
        else { const unsigned char* b = (const unsigned char*)mw1;
               for (int i = 0; i < 10; i++) mm1[i] = (b[i] != 0); }
        if (w32_2) { for (int i = 0; i < 10; i++) mm2[i] = (mw2[i] != 0u); }
        else { const unsigned char* b = (const unsigned char*)mw2;
               for (int i = 0; i < 10; i++) mm2[i] = (b[i] != 0); }
    }

    float ahr[NS];
    {
        bool g1 = (fabsf(om - 0.4f) < 1e-3f) || (fabsf(om - 0.8f) < 1e-3f);
        float scale = g1 ? 0.2f : 0.4f;
        float base = (om - 0.6f) / scale;
        #pragma unroll
        for (int t = 0; t < NS; t++) {
            int tm = g1 ? mm1[t] : mm2[t];
            ahr[t] = (tm ? base : 0.0f) + nz[t];
        }
    }

    // ================= rollout: registers + shfl only ======================
    float s = 0.0f, c = 0.0f, err = 0.0f;
    float hh[NH];
    #pragma unroll
    for (int k = 0; k < NH; k++) hh[k] = 0.0f;

    #pragma unroll
    for (int t = 0; t < NS; t++) {
        float ah = ahr[t];

        float gia = fmaf(ah, vi.y, bi), gib = 0.0f;
        float gfa = fmaf(ah, vf.y, bf), gfb = 0.0f;
        float gga = fmaf(ah, vg.y, bg), ggb = 0.0f;
        float goa = fmaf(ah, vo.y, bo), gob = 0.0f;
        #pragma unroll
        for (int k = 0; k < 5; k++) {
            gia = fmaf(hh[k], whh_i[k], gia);  gib = fmaf(hh[k+5], whh_i[k+5], gib);
            gfa = fmaf(hh[k], whh_f[k], gfa);  gfb = fmaf(hh[k+5], whh_f[k+5], gfb);
            gga = fmaf(hh[k], whh_g[k], gga);  ggb = fmaf(hh[k+5], whh_g[k+5], ggb);
            goa = fmaf(hh[k], whh_o[k], goa);  gob = fmaf(hh[k+5], whh_o[k+5], gob);
        }
        float gi = fsig_pre(fmaf(s, vi.x, gia + gib));
        float gf = fsig_pre(fmaf(s, vf.x, gfa + gfb));
        float gg = mtanh   (fmaf(s, vg.x, gga + ggb));
        float go = fsig_pre(fmaf(s, vo.x, goa + gob));
        c = fmaf(gf, c, gi * gg);
        float h = go * mtanh(c);

        // comm round 1: gather h
        #pragma unroll
        for (int k = 0; k < NH; k++) hh[k] = __shfl_sync(FULLM, h, k);

        float h1a = rb1, h1b = 0.0f;
        #pragma unroll
        for (int k = 0; k < 5; k++) {
            h1a = fmaf(hh[k],   rw1[k],   h1a);
            h1b = fmaf(hh[k+5], rw1[k+5], h1b);
        }
        float h1 = fmaxf(h1a + h1b, 0.0f);

        // comm round 2: gather h1
        float g1v[20];
        #pragma unroll
        for (int k = 0; k < 20; k++) g1v[k] = __shfl_sync(FULLM, h1, k);

        float h2a = rb2, h2b = 0.0f, h2c = 0.0f, h2d = 0.0f;
        #pragma unroll
        for (int k = 0; k < 5; k++) {
            h2a = fmaf(g1v[k],    rw2[k],    h2a);
            h2b = fmaf(g1v[k+5],  rw2[k+5],  h2b);
            h2c = fmaf(g1v[k+10], rw2[k+10], h2c);
            h2d = fmaf(g1v[k+15], rw2[k+15], h2d);
        }
        float h2 = fmaxf((h2a + h2b) + (h2c + h2d), 0.0f);

        // comm round 3: gather h2, redundant dot in all lanes
        float g2v[20];
        #pragma unroll
        for (int k = 0; k < 20; k++) g2v[k] = __shfl_sync(FULLM, h2, k);

        float ra = rb3, rb = 0.0f, rc = 0.0f, rd = 0.0f;
        #pragma unroll
        for (int k = 0; k < 5; k++) {
            ra = fmaf(g2v[k],    rw3[k],    ra);
            rb = fmaf(g2v[k+5],  rw3[k+5],  rb);
            rc = fmaf(g2v[k+10], rw3[k+10], rc);
            rd = fmaf(g2v[k+15], rw3[k+15], rd);
        }
        float ar = (ra + rb) + (rc + rd);

        s += ar;
        float d = s - om;
        err = fmaf(d, d, err);
    }

    // ===== deterministic cross-block reduction: integer fixed-point =======
    // err >= 0; round(err * 2^32) is exact in double and order-independent
    // when summed with integer atomics -> bit-deterministic output.
    if (lane == 0) {
        unsigned long long v =
            (unsigned long long)__double2ll_rn((double)err * 4294967296.0);
        // fire-and-forget reduce (REDG, no return)
        asm volatile("red.relaxed.gpu.add.u64 [%0], %1;"
                     :: "l"(&g_sum), "l"(v) : "memory");
        // ticket with acq_rel: release orders my red; acquire (for the
        // winner) makes all other blocks' reds visible.
        unsigned int old;
        asm volatile("atom.acq_rel.gpu.add.u32 %0, [%1], %2;"
                     : "=r"(old) : "l"(&g_cnt), "r"(1u) : "memory");
        if (old == NT - 1u) {
            unsigned long long sum;
            asm volatile("ld.relaxed.gpu.u64 %0, [%1];"
                         : "=l"(sum) : "l"(&g_sum) : "memory");
            out[0] = (float)((double)(long long)sum * (1.0 / 4294967296.0));
            // reset scratch for the next (graph-replayed) call
            unsigned long long z64 = 0ull; unsigned int z32 = 0u;
            asm volatile("st.relaxed.gpu.u64 [%0], %1;"
                         :: "l"(&g_sum), "l"(z64) : "memory");
            asm volatile("st.relaxed.gpu.u32 [%0], %1;"
                         :: "l"(&g_cnt), "r"(z32) : "memory");
        }
    }
}

extern "C" void kernel_launch(void* const* d_in, const int* in_sizes, int n_in,
                              void* d_out, int out_size) {
    const float* omega = (const float*)d_in[0];
    const float* noise = (const float*)d_in[1];
    const void*  go1   = (const void*)d_in[2];
    const void*  go2   = (const void*)d_in[3];
    const float* W_ih  = (const float*)d_in[4];
    const float* W_hh  = (const float*)d_in[5];
    const float* b_ih  = (const float*)d_in[6];
    const float* b_hh  = (const float*)d_in[7];
    const float* w1    = (const float*)d_in[8];
    const float* b1    = (const float*)d_in[9];
    const float* w2    = (const float*)d_in[10];
    const float* b2    = (const float*)d_in[11];
    const float* w3    = (const float*)d_in[12];
    const float* b3    = (const float*)d_in[13];
    float* out = (float*)d_out;

    rnnae_kernel<<<NT, 32>>>(omega, noise, go1, go2, W_ih, W_hh, b_ih, b_hh,
                             w1, b1, w2, b2, w3, b3, out);
}

// round 8
// speedup vs baseline: 1.2694x; 1.0037x over previous
#include <cuda_runtime.h>
#include <cuda_bf16.h>

#define NH 10
#define NT 5
#define NS 10
#define FULLM 0xffffffffu

// MUFU.TANH: single-instruction tanh.
__device__ __forceinline__ float mtanh(float x) {
    float y;
    asm("tanh.approx.f32 %0, %1;" : "=f"(y) : "f"(x));
    return y;
}
// sigmoid with the 0.5 input pre-scale folded into the weights:
// caller passes z = 0.5*x  ->  sigma(x) = 0.5*tanh(z) + 0.5
__device__ __forceinline__ float fsig_pre(float z) {
    return fmaf(0.5f, mtanh(z), 0.5f);
}
// integer warp reduction (sm_80+): single instruction, order-independent.
__device__ __forceinline__ int warp_redux_s32(int v) {
    int r;
    asm volatile("redux.sync.add.s32 %0, %1, 0xffffffff;" : "=r"(r) : "r"(v));
    return r;
}

// single fused accumulator: [63:56] = arrival count, [55:0] = sum(err)*2^40.
// Integer addition -> order-independent -> bit-deterministic.
__device__ unsigned long long g_acc = 0ull;

__global__ void __launch_bounds__(32, 1)
rnnae_kernel(const float* __restrict__ omega,
             const float* __restrict__ noise,
             const void*  __restrict__ go1_raw,
             const void*  __restrict__ go2_raw,
             const float* __restrict__ W_ih,   // [40,2]
             const float* __restrict__ W_hh,   // [40,10]
             const float* __restrict__ b_ih,   // [40]
             const float* __restrict__ b_hh,   // [40]
             const float* __restrict__ w1,     // [20,10]
             const float* __restrict__ b1,     // [20]
             const float* __restrict__ w2,     // [20,20]
             const float* __restrict__ b2,     // [20]
             const float* __restrict__ w3,     // [1,20]
             const float* __restrict__ b3,     // [1]
             float* __restrict__ out)
{
    const int task = blockIdx.x;            // one task per block (per SM)
    const int lane = threadIdx.x;
    const int j = (lane < NH) ? lane : 0;   // hidden index owned by this lane
    const int m = (lane < 20) ? lane : 0;   // MLP index owned by this lane

    // ============ vectorized global -> register prologue ==================
    // sigmoid gates (i,f,o) are pre-scaled by 0.5; tanh gate (g) is not.
    float2 vi = *(const float2*)(W_ih + 2*j);
    float2 vf = *(const float2*)(W_ih + 2*(10+j));
    float2 vg = *(const float2*)(W_ih + 2*(20+j));
    float2 vo = *(const float2*)(W_ih + 2*(30+j));
    vi.x *= 0.5f; vi.y *= 0.5f;
    vf.x *= 0.5f; vf.y *= 0.5f;
    vo.x *= 0.5f; vo.y *= 0.5f;

    float whh_i[NH], whh_f[NH], whh_g[NH], whh_o[NH], rw1[NH];
    #pragma unroll
    for (int k = 0; k < 5; k++) {
        float2 a  = *(const float2*)(W_hh + j*NH + 2*k);
        float2 b  = *(const float2*)(W_hh + (10+j)*NH + 2*k);
        float2 cc = *(const float2*)(W_hh + (20+j)*NH + 2*k);
        float2 d  = *(const float2*)(W_hh + (30+j)*NH + 2*k);
        float2 e  = *(const float2*)(w1 + m*NH + 2*k);
        whh_i[2*k] = 0.5f*a.x;  whh_i[2*k+1] = 0.5f*a.y;
        whh_f[2*k] = 0.5f*b.x;  whh_f[2*k+1] = 0.5f*b.y;
        whh_g[2*k] = cc.x;      whh_g[2*k+1] = cc.y;
        whh_o[2*k] = 0.5f*d.x;  whh_o[2*k+1] = 0.5f*d.y;
        rw1[2*k]   = e.x;       rw1[2*k+1]   = e.y;
    }

    float bi = 0.5f*(b_ih[j]    + b_hh[j]);
    float bf = 0.5f*(b_ih[10+j] + b_hh[10+j]);
    float bg =       b_ih[20+j] + b_hh[20+j];
    float bo = 0.5f*(b_ih[30+j] + b_hh[30+j]);

    float rw2[20];
    #pragma unroll
    for (int k = 0; k < 5; k++) {
        float4 a = *(const float4*)(w2 + m*20 + 4*k);
        rw2[4*k] = a.x; rw2[4*k+1] = a.y; rw2[4*k+2] = a.z; rw2[4*k+3] = a.w;
    }
    float rb1 = b1[m], rb2 = b2[m], rb3 = b3[0];
    float rw3m = (lane < 20) ? w3[m] : 0.0f;   // only own coefficient needed

    const float om = omega[task];

    float nz[NS];
    #pragma unroll
    for (int k = 0; k < 5; k++) {
        float2 a = *(const float2*)(noise + task*NS + 2*k);
        nz[2*k] = a.x; nz[2*k+1] = a.y;
    }

    // masks (dtype-agnostic decode: f32 / i32 / packed u8)
    unsigned int mw1[10], mw2[10];
    {
        const uint4* p1 = (const uint4*)go1_raw;
        const uint4* p2 = (const uint4*)go2_raw;
        uint4 a = p1[0], b = p1[1];
        uint2 c1 = *(const uint2*)((const unsigned int*)go1_raw + 8);
        uint4 d = p2[0], e = p2[1];
        uint2 c2 = *(const uint2*)((const unsigned int*)go2_raw + 8);
        mw1[0]=a.x; mw1[1]=a.y; mw1[2]=a.z; mw1[3]=a.w;
        mw1[4]=b.x; mw1[5]=b.y; mw1[6]=b.z; mw1[7]=b.w;
        mw1[8]=c1.x; mw1[9]=c1.y;
        mw2[0]=d.x; mw2[1]=d.y; mw2[2]=d.z; mw2[3]=d.w;
        mw2[4]=e.x; mw2[5]=e.y; mw2[6]=e.z; mw2[7]=e.w;
        mw2[8]=c2.x; mw2[9]=c2.y;
    }
    int mm1[10], mm2[10];
    {
        bool w32_1 = true, w32_2 = true;
        #pragma unroll
        for (int i = 0; i < 10; i++) {
            unsigned int v1 = mw1[i], v2 = mw2[i];
            if (v1 != 0u && v1 != 0x3F800000u && v1 != 1u) w32_1 = false;
            if (v2 != 0u && v2 != 0x3F800000u && v2 != 1u) w32_2 = false;
        }
        if (w32_1) { for (int i = 0; i < 10; i++) mm1[i] = (mw1[i] != 0u); }
        else { const unsigned char* b = (const unsigned char*)mw1;
               for (int i = 0; i < 10; i++) mm1[i] = (b[i] != 0); }
        if (w32_2) { for (int i = 0; i < 10; i++) mm2[i] = (mw2[i] != 0u); }
        else { const unsigned char* b = (const unsigned char*)mw2;
               for (int i = 0; i < 10; i++) mm2[i] = (b[i] != 0); }
    }

    float ahr[NS];
    {
        bool g1 = (fabsf(om - 0.4f) < 1e-3f) || (fabsf(om - 0.8f) < 1e-3f);
        float scale = g1 ? 0.2f : 0.4f;
        float base = (om - 0.6f) / scale;
        #pragma unroll
        for (int t = 0; t < NS; t++) {
            int tm = g1 ? mm1[t] : mm2[t];
            ahr[t] = (tm ? base : 0.0f) + nz[t];
        }
    }

    // ================= rollout: registers + shfl/redux only ================
    float s = 0.0f, c = 0.0f, err = 0.0f;
    float hh[NH];
    #pragma unroll
    for (int k = 0; k < NH; k++) hh[k] = 0.0f;

    #pragma unroll
    for (int t = 0; t < NS; t++) {
        float ah = ahr[t];

        float gia = fmaf(ah, vi.y, bi), gib = 0.0f;
        float gfa = fmaf(ah, vf.y, bf), gfb = 0.0f;
        float gga = fmaf(ah, vg.y, bg), ggb = 0.0f;
        float goa = fmaf(ah, vo.y, bo), gob = 0.0f;
        #pragma unroll
        for (int k = 0; k < 5; k++) {
            gia = fmaf(hh[k], whh_i[k], gia);  gib = fmaf(hh[k+5], whh_i[k+5], gib);
            gfa = fmaf(hh[k], whh_f[k], gfa);  gfb = fmaf(hh[k+5], whh_f[k+5], gfb);
            gga = fmaf(hh[k], whh_g[k], gga);  ggb = fmaf(hh[k+5], whh_g[k+5], ggb);
            goa = fmaf(hh[k], whh_o[k], goa);  gob = fmaf(hh[k+5], whh_o[k+5], gob);
        }
        float gi = fsig_pre(fmaf(s, vi.x, gia + gib));
        float gf = fsig_pre(fmaf(s, vf.x, gfa + gfb));
        float gg = mtanh   (fmaf(s, vg.x, gga + ggb));
        float go = fsig_pre(fmaf(s, vo.x, goa + gob));
        c = fmaf(gf, c, gi * gg);
        float h = go * mtanh(c);

        // comm round 1: gather h
        #pragma unroll
        for (int k = 0; k < NH; k++) hh[k] = __shfl_sync(FULLM, h, k);

        float h1a = rb1, h1b = 0.0f;
        #pragma unroll
        for (int k = 0; k < 5; k++) {
            h1a = fmaf(hh[k],   rw1[k],   h1a);
            h1b = fmaf(hh[k+5], rw1[k+5], h1b);
        }
        float h1 = fmaxf(h1a + h1b, 0.0f);

        // comm round 2: gather h1
        float g1v[20];
        #pragma unroll
        for (int k = 0; k < 20; k++) g1v[k] = __shfl_sync(FULLM, h1, k);

        float h2a = rb2, h2b = 0.0f, h2c = 0.0f, h2d = 0.0f;
        #pragma unroll
        for (int k = 0; k < 5; k++) {
            h2a = fmaf(g1v[k],    rw2[k],    h2a);
            h2b = fmaf(g1v[k+5],  rw2[k+5],  h2b);
            h2c = fmaf(g1v[k+10], rw2[k+10], h2c);
            h2d = fmaf(g1v[k+15], rw2[k+15], h2d);
        }
        float h2 = fmaxf((h2a + h2b) + (h2c + h2d), 0.0f);

        // comm round 3: single integer warp-reduce of h2[m]*w3[m] in
        // 2^21 fixed point (exact integer sum -> deterministic; quantization
        // ~5e-7 absolute on ar, far below the 1e-3 gate).
        float p = h2 * rw3m;                       // lanes >=20 have rw3m=0
        int   pi = __float2int_rn(p * 2097152.0f); // *2^21
        int   ps = warp_redux_s32(pi);
        float ar = fmaf((float)ps, 4.7683716e-7f, rb3);  // *2^-21

        s += ar;
        float d = s - om;
        err = fmaf(d, d, err);
    }

    // ===== deterministic cross-block reduction: one fused 64-bit atomic ====
    // val = (1<<56) + round(err*2^40). The winner's returned `old` already
    // contains the other four contributions -> no extra global load.
    if (lane == 0) {
        unsigned long long payload =
            (unsigned long long)__double2ll_rn((double)err * 1099511627776.0); // 2^40
        unsigned long long val = (1ull << 56) + payload;
        unsigned long long old;
        asm volatile("atom.acq_rel.gpu.add.u64 %0, [%1], %2;"
                     : "=l"(old) : "l"(&g_acc), "l"(val) : "memory");
        if ((old >> 56) == (unsigned long long)(NT - 1)) {
            unsigned long long total = (old + val) & ((1ull << 56) - 1ull);
            out[0] = (float)((double)total * (1.0 / 1099511627776.0));
            // reset for the next graph replay (stream-ordered before it)
            unsigned long long z = 0ull;
            asm volatile("st.relaxed.gpu.u64 [%0], %1;"
                         :: "l"(&g_acc), "l"(z) : "memory");
        }
    }
}

extern "C" void kernel_launch(void* const* d_in, const int* in_sizes, int n_in,
                              void* d_out, int out_size) {
    const float* omega = (const float*)d_in[0];
    const float* noise = (const float*)d_in[1];
    const void*  go1   = (const void*)d_in[2];
    const void*  go2   = (const void*)d_in[3];
    const float* W_ih  = (const float*)d_in[4];
    const float* W_hh  = (const float*)d_in[5];
    const float* b_ih  = (const float*)d_in[6];
    const float* b_hh  = (const float*)d_in[7];
    const float* w1    = (const float*)d_in[8];
    const float* b1    = (const float*)d_in[9];
    const float* w2    = (const float*)d_in[10];
    const float* b2    = (const float*)d_in[11];
    const float* w3    = (const float*)d_in[12];
    const float* b3    = (const float*)d_in[13];
    float* out = (float*)d_out;

    rnnae_kernel<<<NT, 32>>>(omega, noise, go1, go2, W_ih, W_hh, b_ih, b_hh,
                             w1, b1, w2, b2, w3, b3, out);
}

// round 9
// speedup vs baseline: 1.3282x; 1.0463x over previous
#include <cuda_runtime.h>
#include <cuda_bf16.h>

#define NH 10
#define NT 5
#define NS 10
#define FULLM 0xffffffffu

// MUFU.TANH: single-instruction tanh.
__device__ __forceinline__ float mtanh(float x) {
    float y;
    asm("tanh.approx.f32 %0, %1;" : "=f"(y) : "f"(x));
    return y;
}
// sigmoid with the 0.5 input pre-scale folded into the weights:
// caller passes z = 0.5*x  ->  sigma(x) = 0.5*tanh(z) + 0.5
__device__ __forceinline__ float fsig_pre(float z) {
    return fmaf(0.5f, mtanh(z), 0.5f);
}
// integer warp reduction (sm_80+): single instruction, order-independent.
__device__ __forceinline__ int warp_redux_s32(int v) {
    int r;
    asm volatile("redux.sync.add.s32 %0, %1, 0xffffffff;" : "=r"(r) : "r"(v));
    return r;
}

// single fused accumulator: [63:56] = arrival count, [55:0] = sum(err)*2^40.
__device__ unsigned long long g_acc = 0ull;

__global__ void __launch_bounds__(32, 1)
rnnae_kernel(const float* __restrict__ omega,
             const float* __restrict__ noise,
             const void*  __restrict__ go1_raw,
             const void*  __restrict__ go2_raw,
             const float* __restrict__ W_ih,   // [40,2]
             const float* __restrict__ W_hh,   // [40,10]
             const float* __restrict__ b_ih,   // [40]
             const float* __restrict__ b_hh,   // [40]
             const float* __restrict__ w1,     // [20,10]
             const float* __restrict__ b1,     // [20]
             const float* __restrict__ w2,     // [20,20]
             const float* __restrict__ b2,     // [20]
             const float* __restrict__ w3,     // [1,20]
             const float* __restrict__ b3,     // [1]
             float* __restrict__ out)
{
    const int task = blockIdx.x;            // one task per block (per SM)
    const int lane = threadIdx.x;
    const int j = (lane < NH) ? lane : 0;   // hidden index owned by this lane
    const int m = (lane < 20) ? lane : 0;   // MLP index owned by this lane

    // ============ prologue: loads issued in NEED order ====================
    // (L1tex completes in issue order: scalars/masks/LSTM weights first,
    //  MLP weights last — they're not consumed until ~100cy into step 0.)

    // -- needed first: omega, noise, masks --
    const float om = omega[task];

    float nz[NS];
    #pragma unroll
    for (int k = 0; k < 5; k++) {
        float2 a = *(const float2*)(noise + task*NS + 2*k);
        nz[2*k] = a.x; nz[2*k+1] = a.y;
    }

    unsigned int mw1[10], mw2[10];
    {
        const uint4* p1 = (const uint4*)go1_raw;
        const uint4* p2 = (const uint4*)go2_raw;
        uint4 a = p1[0], b = p1[1];
        uint2 c1 = *(const uint2*)((const unsigned int*)go1_raw + 8);
        uint4 d = p2[0], e = p2[1];
        uint2 c2 = *(const uint2*)((const unsigned int*)go2_raw + 8);
        mw1[0]=a.x; mw1[1]=a.y; mw1[2]=a.z; mw1[3]=a.w;
        mw1[4]=b.x; mw1[5]=b.y; mw1[6]=b.z; mw1[7]=b.w;
        mw1[8]=c1.x; mw1[9]=c1.y;
        mw2[0]=d.x; mw2[1]=d.y; mw2[2]=d.z; mw2[3]=d.w;
        mw2[4]=e.x; mw2[5]=e.y; mw2[6]=e.z; mw2[7]=e.w;
        mw2[8]=c2.x; mw2[9]=c2.y;
    }

    // -- needed at step-0 gates: LSTM weights/biases --
    float2 vi = *(const float2*)(W_ih + 2*j);
    float2 vf = *(const float2*)(W_ih + 2*(10+j));
    float2 vg = *(const float2*)(W_ih + 2*(20+j));
    float2 vo = *(const float2*)(W_ih + 2*(30+j));
    vi.x *= 0.5f; vi.y *= 0.5f;
    vf.x *= 0.5f; vf.y *= 0.5f;
    vo.x *= 0.5f; vo.y *= 0.5f;

    float whh_i[NH], whh_f[NH], whh_g[NH], whh_o[NH];
    #pragma unroll
    for (int k = 0; k < 5; k++) {
        float2 a  = *(const float2*)(W_hh + j*NH + 2*k);
        float2 b  = *(const float2*)(W_hh + (10+j)*NH + 2*k);
        float2 cc = *(const float2*)(W_hh + (20+j)*NH + 2*k);
        float2 d  = *(const float2*)(W_hh + (30+j)*NH + 2*k);
        whh_i[2*k] = 0.5f*a.x;  whh_i[2*k+1] = 0.5f*a.y;
        whh_f[2*k] = 0.5f*b.x;  whh_f[2*k+1] = 0.5f*b.y;
        whh_g[2*k] = cc.x;      whh_g[2*k+1] = cc.y;
        whh_o[2*k] = 0.5f*d.x;  whh_o[2*k+1] = 0.5f*d.y;
    }

    float bi = 0.5f*(b_ih[j]    + b_hh[j]);
    float bf = 0.5f*(b_ih[10+j] + b_hh[10+j]);
    float bg =       b_ih[20+j] + b_hh[20+j];
    float bo = 0.5f*(b_ih[30+j] + b_hh[30+j]);

    // -- needed later (after step-0 LSTM): MLP weights --
    float rw1[NH];
    #pragma unroll
    for (int k = 0; k < 5; k++) {
        float2 e = *(const float2*)(w1 + m*NH + 2*k);
        rw1[2*k] = e.x; rw1[2*k+1] = e.y;
    }
    float rb1 = b1[m], rb2 = b2[m], rb3 = b3[0];
    float rw3m = (lane < 20) ? w3[m] : 0.0f;

    float rw2[20];
    #pragma unroll
    for (int k = 0; k < 5; k++) {
        float4 a = *(const float4*)(w2 + m*20 + 4*k);
        rw2[4*k] = a.x; rw2[4*k+1] = a.y; rw2[4*k+2] = a.z; rw2[4*k+3] = a.w;
    }

    // mask decode (dtype-agnostic: f32 / i32 / packed u8) — pure ALU
    int mm1[10], mm2[10];
    {
        bool w32_1 = true, w32_2 = true;
        #pragma unroll
        for (int i = 0; i < 10; i++) {
            unsigned int v1 = mw1[i], v2 = mw2[i];
            if (v1 != 0u && v1 != 0x3F800000u && v1 != 1u) w32_1 = false;
            if (v2 != 0u && v2 != 0x3F800000u && v2 != 1u) w32_2 = false;
        }
        if (w32_1) { for (int i = 0; i < 10; i++) mm1[i] = (mw1[i] != 0u); }
        else { const unsigned char* b = (const unsigned char*)mw1;
               for (int i = 0; i < 10; i++) mm1[i] = (b[i] != 0); }
        if (w32_2) { for (int i = 0; i < 10; i++) mm2[i] = (mw2[i] != 0u); }
        else { const unsigned char* b = (const unsigned char*)mw2;
               for (int i = 0; i < 10; i++) mm2[i] = (b[i] != 0); }
    }

    float ahr[NS];
    {
        bool g1 = (fabsf(om - 0.4f) < 1e-3f) || (fabsf(om - 0.8f) < 1e-3f);
        float scale = g1 ? 0.2f : 0.4f;
        float base = (om - 0.6f) / scale;
        #pragma unroll
        for (int t = 0; t < NS; t++) {
            int tm = g1 ? mm1[t] : mm2[t];
            ahr[t] = (tm ? base : 0.0f) + nz[t];
        }
    }

    // ================= rollout: registers + shfl/redux only ================
    float s = 0.0f, c = 0.0f, err = 0.0f;
    float hh[NH];
    #pragma unroll
    for (int k = 0; k < NH; k++) hh[k] = 0.0f;

    #pragma unroll
    for (int t = 0; t < NS; t++) {
        float ah = ahr[t];

        float gia = fmaf(ah, vi.y, bi), gib = 0.0f;
        float gfa = fmaf(ah, vf.y, bf), gfb = 0.0f;
        float gga = fmaf(ah, vg.y, bg), ggb = 0.0f;
        float goa = fmaf(ah, vo.y, bo), gob = 0.0f;
        #pragma unroll
        for (int k = 0; k < 5; k++) {
            gia = fmaf(hh[k], whh_i[k], gia);  gib = fmaf(hh[k+5], whh_i[k+5], gib);
            gfa = fmaf(hh[k], whh_f[k], gfa);  gfb = fmaf(hh[k+5], whh_f[k+5], gfb);
            gga = fmaf(hh[k], whh_g[k], gga);  ggb = fmaf(hh[k+5], whh_g[k+5], ggb);
            goa = fmaf(hh[k], whh_o[k], goa);  gob = fmaf(hh[k+5], whh_o[k+5], gob);
        }
        // MUFU order: gg first (c-path), then gi, gf; go last (used latest).
        float gg = mtanh   (fmaf(s, vg.x, gga + ggb));
        float gi = fsig_pre(fmaf(s, vi.x, gia + gib));
        float gf = fsig_pre(fmaf(s, vf.x, gfa + gfb));
        float go = fsig_pre(fmaf(s, vo.x, goa + gob));
        c = fmaf(gf, c, gi * gg);
        float h = go * mtanh(c);

        // comm round 1: gather h
        #pragma unroll
        for (int k = 0; k < NH; k++) hh[k] = __shfl_sync(FULLM, h, k);

        float h1a = rb1, h1b = 0.0f;
        #pragma unroll
        for (int k = 0; k < 5; k++) {
            h1a = fmaf(hh[k],   rw1[k],   h1a);
            h1b = fmaf(hh[k+5], rw1[k+5], h1b);
        }
        float h1 = fmaxf(h1a + h1b, 0.0f);

        // comm round 2: gather h1
        float g1v[20];
        #pragma unroll
        for (int k = 0; k < 20; k++) g1v[k] = __shfl_sync(FULLM, h1, k);

        float h2a = rb2, h2b = 0.0f, h2c = 0.0f, h2d = 0.0f;
        #pragma unroll
        for (int k = 0; k < 5; k++) {
            h2a = fmaf(g1v[k],    rw2[k],    h2a);
            h2b = fmaf(g1v[k+5],  rw2[k+5],  h2b);
            h2c = fmaf(g1v[k+10], rw2[k+10], h2c);
            h2d = fmaf(g1v[k+15], rw2[k+15], h2d);
        }
        float h2 = fmaxf((h2a + h2b) + (h2c + h2d), 0.0f);

        // comm round 3: integer warp-reduce of h2[m]*w3[m] in 2^19 fixed
        // point; float<->int via magic-number (FFMA/IADD/FADD, no F2I/I2F).
        float p = h2 * rw3m;                            // lanes >=20: 0
        float yq = fmaf(p, 524288.0f, 12582912.0f);     // p*2^19 + 1.5*2^23
        int   pi = __float_as_int(yq) - 0x4B400000;     // rn(p*2^19)
        int   ps = warp_redux_s32(pi);
        float rf = __int_as_float(ps + 0x4B400000) - 12582912.0f;  // (float)ps
        float ar = fmaf(rf, 1.9073486328125e-6f, rb3);  // *2^-19 + b3

        s += ar;
        float d = s - om;
        err = fmaf(d, d, err);
    }

    // ===== deterministic cross-block reduction: one fused 64-bit atomic ====
    if (lane == 0) {
        unsigned long long payload =
            (unsigned long long)__double2ll_rn((double)err * 1099511627776.0); // 2^40
        unsigned long long val = (1ull << 56) + payload;
        unsigned long long old;
        asm volatile("atom.acq_rel.gpu.add.u64 %0, [%1], %2;"
                     : "=l"(old) : "l"(&g_acc), "l"(val) : "memory");
        if ((old >> 56) == (unsigned long long)(NT - 1)) {
            unsigned long long total = (old + val) & ((1ull << 56) - 1ull);
            out[0] = (float)((double)total * (1.0 / 1099511627776.0));
            unsigned long long z = 0ull;
            asm volatile("st.relaxed.gpu.u64 [%0], %1;"
                         :: "l"(&g_acc), "l"(z) : "memory");
        }
    }
}

extern "C" void kernel_launch(void* const* d_in, const int* in_sizes, int n_in,
                              void* d_out, int out_size) {
    const float* omega = (const float*)d_in[0];
    const float* noise = (const float*)d_in[1];
    const void*  go1   = (const void*)d_in[2];
    const void*  go2   = (const void*)d_in[3];
    const float* W_ih  = (const float*)d_in[4];
    const float* W_hh  = (const float*)d_in[5];
    const float* b_ih  = (const float*)d_in[6];
    const float* b_hh  = (const float*)d_in[7];
    const float* w1    = (const float*)d_in[8];
    const float* b1    = (const float*)d_in[9];
    const float* w2    = (const float*)d_in[10];
    const float* b2    = (const float*)d_in[11];
    const float* w3    = (const float*)d_in[12];
    const float* b3    = (const float*)d_in[13];
    float* out = (float*)d_out;

    rnnae_kernel<<<NT, 32>>>(omega, noise, go1, go2, W_ih, W_hh, b_ih, b_hh,
                             w1, b1, w2, b2, w3, b3, out);
}